// round 1
// baseline (speedup 1.0000x reference)
#include <cuda_runtime.h>
#include <math.h>

#define T_STEPS 128
#define BATCH   256
#define OBSD    512
#define ENCD    256
#define HID     512
#define NACT    18
#define NTOT    (T_STEPS * BATCH)   // 32768

// ---------------- scratch (static device globals; no runtime allocation) ----
__device__ float g_h1[(size_t)NTOT * ENCD];          // 32 MB
__device__ float g_h2[(size_t)NTOT * ENCD];          // 32 MB
__device__ float g_gx[(size_t)NTOT * 3 * HID];       // 201 MB
__device__ float g_hidden[(size_t)NTOT * HID];       // 64 MB
__device__ float g_state[2][BATCH * HID];            // ping-pong GRU state

// ---------------------------------------------------------------------------
// Generic C[M,Nc] = act(A[M,K] @ W[Nc,K]^T + bias)   (both operands K-major)
// BM=128, BN=64, BK=16, 256 threads, thread tile 8x4
// ---------------------------------------------------------------------------
template <bool RELU>
__global__ __launch_bounds__(256)
void gemm_nt_kernel(const float* __restrict__ A,
                    const float* __restrict__ W,
                    const float* __restrict__ bias,
                    float* __restrict__ C,
                    int M, int Nc, int K)
{
    const int BM = 128, BN = 64, BK = 16;
    __shared__ float As[BK][BM];
    __shared__ float Ws[BK][BN];

    const int tid = threadIdx.x;
    const int tx  = tid & 15;        // 16 cols of threads (TN=4)
    const int ty  = tid >> 4;        // 16 rows of threads (TM=8)
    const int row0 = blockIdx.y * BM;
    const int col0 = blockIdx.x * BN;

    float acc[8][4];
#pragma unroll
    for (int i = 0; i < 8; i++)
#pragma unroll
        for (int j = 0; j < 4; j++) acc[i][j] = 0.f;

    for (int k0 = 0; k0 < K; k0 += BK) {
        // load A tile: 128x16 = 512 float4, 2 per thread
#pragma unroll
        for (int l = 0; l < 2; l++) {
            int i  = tid + l * 256;
            int r  = i >> 2;             // 0..127
            int c4 = i & 3;              // 0..3
            float4 v = *(const float4*)(A + (size_t)(row0 + r) * K + k0 + c4 * 4);
            As[c4 * 4 + 0][r] = v.x;
            As[c4 * 4 + 1][r] = v.y;
            As[c4 * 4 + 2][r] = v.z;
            As[c4 * 4 + 3][r] = v.w;
        }
        // load W tile: 64x16 = 256 float4, 1 per thread
        {
            int r  = tid >> 2;           // 0..63
            int c4 = tid & 3;
            float4 v = *(const float4*)(W + (size_t)(col0 + r) * K + k0 + c4 * 4);
            Ws[c4 * 4 + 0][r] = v.x;
            Ws[c4 * 4 + 1][r] = v.y;
            Ws[c4 * 4 + 2][r] = v.z;
            Ws[c4 * 4 + 3][r] = v.w;
        }
        __syncthreads();

#pragma unroll
        for (int k = 0; k < BK; k++) {
            float4 a0 = *(const float4*)&As[k][ty * 8];
            float4 a1 = *(const float4*)&As[k][ty * 8 + 4];
            float4 b  = *(const float4*)&Ws[k][tx * 4];
            float af[8] = {a0.x, a0.y, a0.z, a0.w, a1.x, a1.y, a1.z, a1.w};
            float bf[4] = {b.x, b.y, b.z, b.w};
#pragma unroll
            for (int i = 0; i < 8; i++)
#pragma unroll
                for (int j = 0; j < 4; j++) acc[i][j] += af[i] * bf[j];
        }
        __syncthreads();
    }

#pragma unroll
    for (int i = 0; i < 8; i++) {
        int r = row0 + ty * 8 + i;
#pragma unroll
        for (int j = 0; j < 4; j++) {
            int c = col0 + tx * 4 + j;
            float v = acc[i][j] + bias[c];
            if (RELU) v = fmaxf(v, 0.f);
            C[(size_t)r * Nc + c] = v;
        }
    }
}

// ---------------------------------------------------------------------------
// One GRU timestep, fused: gh = (h_prev * (1-done)) @ w_hh^T + b_hh, gates,
// h_new written to state_out and g_hidden.
// Tile: 32 batch rows x 32 h-cols (x 3 gates), 256 threads, BK=32.
// Grid: (HID/32, BATCH/32) = (16, 8)
// ---------------------------------------------------------------------------
__global__ __launch_bounds__(256)
void gru_step_kernel(const float* __restrict__ state_in,
                     float* __restrict__ state_out,
                     const float* __restrict__ w_hh,
                     const float* __restrict__ b_hh,
                     const float* __restrict__ done,
                     int t)
{
    const int BM = 32, BG = 32, BK = 32;
    __shared__ float As[BK][BM];
    __shared__ float Ws[BK][3 * BG];
    __shared__ float s_mask[BM];

    const int tid = threadIdx.x;
    const int tx  = tid & 15;   // cols (TN=2)
    const int ty  = tid >> 4;   // rows (TM=2)
    const int row0 = blockIdx.y * BM;   // batch offset
    const int col0 = blockIdx.x * BG;   // h-col offset

    if (tid < BM) s_mask[tid] = 1.0f - done[t * BATCH + row0 + tid];
    __syncthreads();

    float acc[3][2][2];
#pragma unroll
    for (int g = 0; g < 3; g++)
#pragma unroll
        for (int i = 0; i < 2; i++)
#pragma unroll
            for (int j = 0; j < 2; j++) acc[g][i][j] = 0.f;

    for (int k0 = 0; k0 < HID; k0 += BK) {
        // A tile: 32x32 = 256 float4, 1 per thread (masked h_prev)
        {
            int r  = tid >> 3;        // 0..31
            int c4 = tid & 7;         // 0..7
            float4 v = *(const float4*)(state_in + (size_t)(row0 + r) * HID + k0 + c4 * 4);
            float m = s_mask[r];
            As[c4 * 4 + 0][r] = v.x * m;
            As[c4 * 4 + 1][r] = v.y * m;
            As[c4 * 4 + 2][r] = v.z * m;
            As[c4 * 4 + 3][r] = v.w * m;
        }
        // W tile: 96x32 = 768 float4, 3 per thread. Row r: gate g=r/32, local col.
#pragma unroll
        for (int l = 0; l < 3; l++) {
            int i  = tid + l * 256;
            int r  = i >> 3;          // 0..95
            int c4 = i & 7;
            int g  = r >> 5;
            int lr = r & 31;
            float4 v = *(const float4*)(w_hh + (size_t)(g * HID + col0 + lr) * HID + k0 + c4 * 4);
            Ws[c4 * 4 + 0][r] = v.x;
            Ws[c4 * 4 + 1][r] = v.y;
            Ws[c4 * 4 + 2][r] = v.z;
            Ws[c4 * 4 + 3][r] = v.w;
        }
        __syncthreads();

#pragma unroll
        for (int k = 0; k < BK; k++) {
            float2 a = *(const float2*)&As[k][ty * 2];
#pragma unroll
            for (int g = 0; g < 3; g++) {
                float2 b = *(const float2*)&Ws[k][g * BG + tx * 2];
                acc[g][0][0] += a.x * b.x;
                acc[g][0][1] += a.x * b.y;
                acc[g][1][0] += a.y * b.x;
                acc[g][1][1] += a.y * b.y;
            }
        }
        __syncthreads();
    }

    const float* gx_t = g_gx + (size_t)t * BATCH * 3 * HID;
#pragma unroll
    for (int i = 0; i < 2; i++) {
        int b = row0 + ty * 2 + i;
        float m = s_mask[ty * 2 + i];
#pragma unroll
        for (int j = 0; j < 2; j++) {
            int c = col0 + tx * 2 + j;
            float ghr = acc[0][i][j] + b_hh[c];
            float ghz = acc[1][i][j] + b_hh[HID + c];
            float ghn = acc[2][i][j] + b_hh[2 * HID + c];
            const float* gxr = gx_t + (size_t)b * 3 * HID;
            float xr = gxr[c];
            float xz = gxr[HID + c];
            float xn = gxr[2 * HID + c];
            float r = 1.f / (1.f + expf(-(xr + ghr)));
            float z = 1.f / (1.f + expf(-(xz + ghz)));
            float hp = state_in[(size_t)b * HID + c] * m;
            float n = tanhf(xn + r * ghn);
            float hnew = (1.f - z) * n + z * hp;
            state_out[(size_t)b * HID + c] = hnew;
            g_hidden[(size_t)(t * BATCH + b) * HID + c] = hnew;
        }
    }
}

// ---------------------------------------------------------------------------
// Heads: one warp per row n. logits -> log_softmax -> log_prob/entropy, value.
// ---------------------------------------------------------------------------
__global__ __launch_bounds__(256)
void heads_kernel(const int* __restrict__ action,
                  const float* __restrict__ w_actor,
                  const float* __restrict__ b_actor,
                  const float* __restrict__ w_critic,
                  const float* __restrict__ b_critic,
                  float* __restrict__ out)
{
    __shared__ float s_wa[NACT * HID];
    __shared__ float s_wc[HID];
    __shared__ float s_ba[NACT];

    const int tid = threadIdx.x;
    for (int i = tid; i < NACT * HID; i += 256) s_wa[i] = w_actor[i];
    for (int i = tid; i < HID; i += 256) s_wc[i] = w_critic[i];
    if (tid < NACT) s_ba[tid] = b_actor[tid];
    __syncthreads();

    const int warp = tid >> 5;
    const int lane = tid & 31;
    const int n = blockIdx.x * 8 + warp;

    const float* hrow = g_hidden + (size_t)n * HID;
    float h[16];
#pragma unroll
    for (int i = 0; i < 16; i++) h[i] = hrow[lane + 32 * i];

    float l[NACT];
#pragma unroll
    for (int a = 0; a < NACT; a++) {
        float p = 0.f;
        const float* wa = s_wa + a * HID;
#pragma unroll
        for (int i = 0; i < 16; i++) p += h[i] * wa[lane + 32 * i];
#pragma unroll
        for (int o = 16; o > 0; o >>= 1) p += __shfl_xor_sync(0xffffffffu, p, o);
        l[a] = p + s_ba[a];
    }

    float v = 0.f;
#pragma unroll
    for (int i = 0; i < 16; i++) v += h[i] * s_wc[lane + 32 * i];
#pragma unroll
    for (int o = 16; o > 0; o >>= 1) v += __shfl_xor_sync(0xffffffffu, v, o);
    v += b_critic[0];

    float m = l[0];
#pragma unroll
    for (int a = 1; a < NACT; a++) m = fmaxf(m, l[a]);
    float s = 0.f;
#pragma unroll
    for (int a = 0; a < NACT; a++) s += expf(l[a] - m);
    float lse = m + logf(s);

    float ent = 0.f;
#pragma unroll
    for (int a = 0; a < NACT; a++) ent += expf(l[a] - lse) * (lse - l[a]);

    int act = action[n];
    float lp = 0.f;
#pragma unroll
    for (int a = 0; a < NACT; a++) lp += (a == act) ? (l[a] - lse) : 0.f;

    if (lane == 0) {
        out[n] = lp;
        out[NTOT + n] = ent;
        out[2 * NTOT + n] = v;
    }
}

__global__ void copy_state_kernel(const float* __restrict__ src, float* __restrict__ dst)
{
    int i = blockIdx.x * 256 + threadIdx.x;
    dst[i] = src[i];
}

// ---------------------------------------------------------------------------
extern "C" void kernel_launch(void* const* d_in, const int* in_sizes, int n_in,
                              void* d_out, int out_size)
{
    const float* x        = (const float*)d_in[0];
    const float* gru_st   = (const float*)d_in[1];
    const float* done     = (const float*)d_in[2];
    const int*   action   = (const int*)  d_in[3];
    const float* w1       = (const float*)d_in[4];
    const float* b1       = (const float*)d_in[5];
    const float* w2       = (const float*)d_in[6];
    const float* b2       = (const float*)d_in[7];
    const float* w_ih     = (const float*)d_in[8];
    const float* w_hh     = (const float*)d_in[9];
    const float* b_ih     = (const float*)d_in[10];
    const float* b_hh     = (const float*)d_in[11];
    const float* w_actor  = (const float*)d_in[12];
    const float* b_actor  = (const float*)d_in[13];
    const float* w_critic = (const float*)d_in[14];
    const float* b_critic = (const float*)d_in[15];
    float* out = (float*)d_out;

    float *h1, *h2, *gx, *st;
    cudaGetSymbolAddress((void**)&h1, g_h1);
    cudaGetSymbolAddress((void**)&h2, g_h2);
    cudaGetSymbolAddress((void**)&gx, g_gx);
    cudaGetSymbolAddress((void**)&st, g_state);
    float* s0 = st;
    float* s1 = st + BATCH * HID;

    // encoder layer 1: (N,512)@(512,256)^T -> h1
    gemm_nt_kernel<true><<<dim3(ENCD / 64, NTOT / 128), 256>>>(
        x, w1, b1, h1, NTOT, ENCD, OBSD);
    // encoder layer 2: (N,256)@(256,256)^T -> h2
    gemm_nt_kernel<true><<<dim3(ENCD / 64, NTOT / 128), 256>>>(
        h1, w2, b2, h2, NTOT, ENCD, ENCD);
    // input-side gates: (N,256)@(256,1536)^T -> gx
    gemm_nt_kernel<false><<<dim3(3 * HID / 64, NTOT / 128), 256>>>(
        h2, w_ih, b_ih, gx, NTOT, 3 * HID, ENCD);

    // GRU scan: 128 sequential fused steps
    for (int t = 0; t < T_STEPS; t++) {
        const float* sin = (t == 0) ? gru_st : ((t & 1) ? s1 : s0);
        float* sout = (t & 1) ? s0 : s1;
        gru_step_kernel<<<dim3(HID / 32, BATCH / 32), 256>>>(
            sin, sout, w_hh, b_hh, done, t);
    }
    // after 128 steps (even), final state is in s0
    copy_state_kernel<<<BATCH * HID / 256, 256>>>(s0, out + 3 * NTOT);

    // heads
    heads_kernel<<<NTOT / 8, 256>>>(action, w_actor, b_actor, w_critic, b_critic, out);
}

// round 2
// speedup vs baseline: 1.4454x; 1.4454x over previous
#include <cuda_runtime.h>
#include <math.h>

#define T_STEPS 128
#define BATCH   256
#define OBSD    512
#define ENCD    256
#define HID     512
#define NACT    18
#define NTOT    (T_STEPS * BATCH)   // 32768

// ---------------- scratch (static device globals; no runtime allocation) ----
__device__ float g_h1[(size_t)NTOT * ENCD];
__device__ float g_h2[(size_t)NTOT * ENCD];
__device__ float g_gx[(size_t)NTOT * 3 * HID];
__device__ float g_hidden[(size_t)NTOT * HID];
__device__ float g_state[2][BATCH * HID];

// ---------------------------------------------------------------------------
// helpers
// ---------------------------------------------------------------------------
__device__ __forceinline__ unsigned f2tf32(float f) {
    unsigned u;
    asm("cvt.rna.tf32.f32 %0, %1;" : "=r"(u) : "f"(f));
    return u;
}

__device__ __forceinline__ void mma_tf32(float d[4], const unsigned a[4], const unsigned b[2]) {
    asm volatile(
        "mma.sync.aligned.m16n8k8.row.col.f32.tf32.tf32.f32 "
        "{%0,%1,%2,%3}, {%4,%5,%6,%7}, {%8,%9}, {%0,%1,%2,%3};"
        : "+f"(d[0]), "+f"(d[1]), "+f"(d[2]), "+f"(d[3])
        : "r"(a[0]), "r"(a[1]), "r"(a[2]), "r"(a[3]), "r"(b[0]), "r"(b[1]));
}

// ---------------------------------------------------------------------------
// Generic C[M,Nc] = act(A[M,K] @ W[Nc,K]^T + bias) using tf32 mma.
// BM=64, BN=64, BK=16, 128 threads (4 warps, 2x2), warptile 32x32.
// ---------------------------------------------------------------------------
template <bool RELU>
__global__ __launch_bounds__(128)
void gemm_tf32_kernel(const float* __restrict__ A,
                      const float* __restrict__ W,
                      const float* __restrict__ bias,
                      float* __restrict__ C,
                      int M, int Nc, int K)
{
    __shared__ float As[64][18];   // [m][k], tf32 bit patterns
    __shared__ float Ws[64][18];   // [n][k]

    const int tid  = threadIdx.x;
    const int warp = tid >> 5;
    const int lane = tid & 31;
    const int g    = lane >> 2;    // group 0..7
    const int tg   = lane & 3;     // 0..3
    const int warp_m = (warp & 1) * 32;
    const int warp_n = (warp >> 1) * 32;
    const int row0 = blockIdx.y * 64;
    const int col0 = blockIdx.x * 64;

    float acc[2][4][4];
#pragma unroll
    for (int i = 0; i < 2; i++)
#pragma unroll
        for (int j = 0; j < 4; j++)
#pragma unroll
            for (int q = 0; q < 4; q++) acc[i][j][q] = 0.f;

    float4 ra[2], rw[2];
    // prefetch tile 0
#pragma unroll
    for (int l = 0; l < 2; l++) {
        int i = tid + l * 128;
        ra[l] = *(const float4*)(A + (size_t)(row0 + (i >> 2)) * K + (i & 3) * 4);
        rw[l] = *(const float4*)(W + (size_t)(col0 + (i >> 2)) * K + (i & 3) * 4);
    }

    for (int k0 = 0; k0 < K; k0 += 16) {
        // STS with tf32 conversion
#pragma unroll
        for (int l = 0; l < 2; l++) {
            int i = tid + l * 128;
            int r = i >> 2, c = (i & 3) * 4;
            As[r][c + 0] = __uint_as_float(f2tf32(ra[l].x));
            As[r][c + 1] = __uint_as_float(f2tf32(ra[l].y));
            As[r][c + 2] = __uint_as_float(f2tf32(ra[l].z));
            As[r][c + 3] = __uint_as_float(f2tf32(ra[l].w));
            Ws[r][c + 0] = __uint_as_float(f2tf32(rw[l].x));
            Ws[r][c + 1] = __uint_as_float(f2tf32(rw[l].y));
            Ws[r][c + 2] = __uint_as_float(f2tf32(rw[l].z));
            Ws[r][c + 3] = __uint_as_float(f2tf32(rw[l].w));
        }
        __syncthreads();

        if (k0 + 16 < K) {
#pragma unroll
            for (int l = 0; l < 2; l++) {
                int i = tid + l * 128;
                ra[l] = *(const float4*)(A + (size_t)(row0 + (i >> 2)) * K + k0 + 16 + (i & 3) * 4);
                rw[l] = *(const float4*)(W + (size_t)(col0 + (i >> 2)) * K + k0 + 16 + (i & 3) * 4);
            }
        }

#pragma unroll
        for (int ks = 0; ks < 16; ks += 8) {
            unsigned af[2][4], bf[4][2];
#pragma unroll
            for (int mf = 0; mf < 2; mf++) {
                int br = warp_m + mf * 16;
                af[mf][0] = __float_as_uint(As[br + g][ks + tg]);
                af[mf][1] = __float_as_uint(As[br + g + 8][ks + tg]);
                af[mf][2] = __float_as_uint(As[br + g][ks + tg + 4]);
                af[mf][3] = __float_as_uint(As[br + g + 8][ks + tg + 4]);
            }
#pragma unroll
            for (int nf = 0; nf < 4; nf++) {
                int bn = warp_n + nf * 8;
                bf[nf][0] = __float_as_uint(Ws[bn + g][ks + tg]);
                bf[nf][1] = __float_as_uint(Ws[bn + g][ks + tg + 4]);
            }
#pragma unroll
            for (int mf = 0; mf < 2; mf++)
#pragma unroll
                for (int nf = 0; nf < 4; nf++) mma_tf32(acc[mf][nf], af[mf], bf[nf]);
        }
        __syncthreads();
    }

    // epilogue
#pragma unroll
    for (int mf = 0; mf < 2; mf++) {
#pragma unroll
        for (int nf = 0; nf < 4; nf++) {
            int r = row0 + warp_m + mf * 16 + g;
            int c = col0 + warp_n + nf * 8 + tg * 2;
            float b0v = bias[c], b1v = bias[c + 1];
            float v0 = acc[mf][nf][0] + b0v;
            float v1 = acc[mf][nf][1] + b1v;
            float v2 = acc[mf][nf][2] + b0v;
            float v3 = acc[mf][nf][3] + b1v;
            if (RELU) {
                v0 = fmaxf(v0, 0.f); v1 = fmaxf(v1, 0.f);
                v2 = fmaxf(v2, 0.f); v3 = fmaxf(v3, 0.f);
            }
            *(float2*)&C[(size_t)r * Nc + c]       = make_float2(v0, v1);
            *(float2*)&C[(size_t)(r + 8) * Nc + c] = make_float2(v2, v3);
        }
    }
}

// ---------------------------------------------------------------------------
// GRU step with tf32 mma.
// Block: 128 threads (4 warps). Tile: BM=32 batch rows, HC=32 h-cols
// -> gemm tile 32 x 96 (rows 0..31 gate r cols, 32..63 z, 64..95 n).
// Warp w handles combined cols [24w, 24w+24) (3 n8-frags), full m=32.
// Grid: (HID/32, BATCH/32) = (16, 8) = 128 blocks.
// ---------------------------------------------------------------------------
__global__ __launch_bounds__(128)
void gru_step_tf32(const float* __restrict__ state_in,
                   float* __restrict__ state_out,
                   const float* __restrict__ w_hh,
                   const float* __restrict__ b_hh,
                   const float* __restrict__ done,
                   int t)
{
    __shared__ float As[32][18];        // [batch][k]
    __shared__ float Bs[96][18];        // [combined col][k]
    __shared__ float gh_s[32][100];     // gh staging (padded)
    __shared__ float s_mask[32];

    const int tid  = threadIdx.x;
    const int warp = tid >> 5;
    const int lane = tid & 31;
    const int g    = lane >> 2;
    const int tg   = lane & 3;
    const int col0 = blockIdx.x * 32;   // h-col block
    const int row0 = blockIdx.y * 32;   // batch block

    if (tid < 32) s_mask[tid] = 1.0f - done[t * BATCH + row0 + tid];
    __syncthreads();

    float acc[2][3][4];
#pragma unroll
    for (int i = 0; i < 2; i++)
#pragma unroll
        for (int j = 0; j < 3; j++)
#pragma unroll
            for (int q = 0; q < 4; q++) acc[i][j][q] = 0.f;

    // register prefetch buffers
    float4 ra;       // A: 32x16 = 128 float4, 1 per thread
    float4 rb[3];    // B: 96x16 = 384 float4, 3 per thread
    float maskA;
    {
        int r = tid >> 2, c4 = tid & 3;
        maskA = s_mask[r];
        ra = *(const float4*)(state_in + (size_t)(row0 + r) * HID + c4 * 4);
#pragma unroll
        for (int l = 0; l < 3; l++) {
            int i = tid + l * 128;
            int cr = i >> 2, c4b = i & 3;
            int gg = cr >> 5, lr = cr & 31;
            rb[l] = *(const float4*)(w_hh + (size_t)(gg * HID + col0 + lr) * HID + c4b * 4);
        }
    }

    for (int k0 = 0; k0 < HID; k0 += 16) {
        {
            int r = tid >> 2, c = (tid & 3) * 4;
            As[r][c + 0] = __uint_as_float(f2tf32(ra.x * maskA));
            As[r][c + 1] = __uint_as_float(f2tf32(ra.y * maskA));
            As[r][c + 2] = __uint_as_float(f2tf32(ra.z * maskA));
            As[r][c + 3] = __uint_as_float(f2tf32(ra.w * maskA));
#pragma unroll
            for (int l = 0; l < 3; l++) {
                int i = tid + l * 128;
                int cr = i >> 2, cc = (i & 3) * 4;
                Bs[cr][cc + 0] = __uint_as_float(f2tf32(rb[l].x));
                Bs[cr][cc + 1] = __uint_as_float(f2tf32(rb[l].y));
                Bs[cr][cc + 2] = __uint_as_float(f2tf32(rb[l].z));
                Bs[cr][cc + 3] = __uint_as_float(f2tf32(rb[l].w));
            }
        }
        __syncthreads();

        if (k0 + 16 < HID) {
            int r = tid >> 2, c4 = tid & 3;
            ra = *(const float4*)(state_in + (size_t)(row0 + r) * HID + k0 + 16 + c4 * 4);
#pragma unroll
            for (int l = 0; l < 3; l++) {
                int i = tid + l * 128;
                int cr = i >> 2, c4b = i & 3;
                int gg = cr >> 5, lr = cr & 31;
                rb[l] = *(const float4*)(w_hh + (size_t)(gg * HID + col0 + lr) * HID + k0 + 16 + c4b * 4);
            }
        }

#pragma unroll
        for (int ks = 0; ks < 16; ks += 8) {
            unsigned af[2][4], bf[3][2];
#pragma unroll
            for (int mf = 0; mf < 2; mf++) {
                int br = mf * 16;
                af[mf][0] = __float_as_uint(As[br + g][ks + tg]);
                af[mf][1] = __float_as_uint(As[br + g + 8][ks + tg]);
                af[mf][2] = __float_as_uint(As[br + g][ks + tg + 4]);
                af[mf][3] = __float_as_uint(As[br + g + 8][ks + tg + 4]);
            }
#pragma unroll
            for (int nf = 0; nf < 3; nf++) {
                int bn = warp * 24 + nf * 8;
                bf[nf][0] = __float_as_uint(Bs[bn + g][ks + tg]);
                bf[nf][1] = __float_as_uint(Bs[bn + g][ks + tg + 4]);
            }
#pragma unroll
            for (int mf = 0; mf < 2; mf++)
#pragma unroll
                for (int nf = 0; nf < 3; nf++) mma_tf32(acc[mf][nf], af[mf], bf[nf]);
        }
        __syncthreads();
    }

    // stage gh into smem
#pragma unroll
    for (int mf = 0; mf < 2; mf++) {
#pragma unroll
        for (int nf = 0; nf < 3; nf++) {
            int r = mf * 16 + g;
            int c = warp * 24 + nf * 8 + tg * 2;
            gh_s[r][c]         = acc[mf][nf][0];
            gh_s[r][c + 1]     = acc[mf][nf][1];
            gh_s[r + 8][c]     = acc[mf][nf][2];
            gh_s[r + 8][c + 1] = acc[mf][nf][3];
        }
    }
    __syncthreads();

    // fused gate math: 128 threads x 8 items cover 32x32
    const int b = tid >> 2;
    const int cbase = (tid & 3) * 8;
    const int bglob = row0 + b;
    const float m = s_mask[b];
    const float* gxr = g_gx + ((size_t)t * BATCH + bglob) * (3 * HID);
#pragma unroll
    for (int u = 0; u < 8; u++) {
        int c = cbase + u;
        int hcol = col0 + c;
        float ghr = gh_s[b][c]      + b_hh[hcol];
        float ghz = gh_s[b][32 + c] + b_hh[HID + hcol];
        float ghn = gh_s[b][64 + c] + b_hh[2 * HID + hcol];
        float xr = gxr[hcol];
        float xz = gxr[HID + hcol];
        float xn = gxr[2 * HID + hcol];
        float r = 1.f / (1.f + expf(-(xr + ghr)));
        float z = 1.f / (1.f + expf(-(xz + ghz)));
        float hp = state_in[(size_t)bglob * HID + hcol] * m;
        float n = tanhf(xn + r * ghn);
        float hnew = (1.f - z) * n + z * hp;
        state_out[(size_t)bglob * HID + hcol] = hnew;
        g_hidden[((size_t)t * BATCH + bglob) * HID + hcol] = hnew;
    }
}

// ---------------------------------------------------------------------------
// Heads: one warp per row n.
// ---------------------------------------------------------------------------
__global__ __launch_bounds__(256)
void heads_kernel(const int* __restrict__ action,
                  const float* __restrict__ w_actor,
                  const float* __restrict__ b_actor,
                  const float* __restrict__ w_critic,
                  const float* __restrict__ b_critic,
                  float* __restrict__ out)
{
    __shared__ float s_wa[NACT * HID];
    __shared__ float s_wc[HID];
    __shared__ float s_ba[NACT];

    const int tid = threadIdx.x;
    for (int i = tid; i < NACT * HID; i += 256) s_wa[i] = w_actor[i];
    for (int i = tid; i < HID; i += 256) s_wc[i] = w_critic[i];
    if (tid < NACT) s_ba[tid] = b_actor[tid];
    __syncthreads();

    const int warp = tid >> 5;
    const int lane = tid & 31;
    const int n = blockIdx.x * 8 + warp;

    const float* hrow = g_hidden + (size_t)n * HID;
    float h[16];
#pragma unroll
    for (int i = 0; i < 16; i++) h[i] = hrow[lane + 32 * i];

    float l[NACT];
#pragma unroll
    for (int a = 0; a < NACT; a++) {
        float p = 0.f;
        const float* wa = s_wa + a * HID;
#pragma unroll
        for (int i = 0; i < 16; i++) p += h[i] * wa[lane + 32 * i];
#pragma unroll
        for (int o = 16; o > 0; o >>= 1) p += __shfl_xor_sync(0xffffffffu, p, o);
        l[a] = p + s_ba[a];
    }

    float v = 0.f;
#pragma unroll
    for (int i = 0; i < 16; i++) v += h[i] * s_wc[lane + 32 * i];
#pragma unroll
    for (int o = 16; o > 0; o >>= 1) v += __shfl_xor_sync(0xffffffffu, v, o);
    v += b_critic[0];

    float mx = l[0];
#pragma unroll
    for (int a = 1; a < NACT; a++) mx = fmaxf(mx, l[a]);
    float s = 0.f;
#pragma unroll
    for (int a = 0; a < NACT; a++) s += expf(l[a] - mx);
    float lse = mx + logf(s);

    float ent = 0.f;
#pragma unroll
    for (int a = 0; a < NACT; a++) ent += expf(l[a] - lse) * (lse - l[a]);

    int act = action[n];
    float lp = 0.f;
#pragma unroll
    for (int a = 0; a < NACT; a++) lp += (a == act) ? (l[a] - lse) : 0.f;

    if (lane == 0) {
        out[n] = lp;
        out[NTOT + n] = ent;
        out[2 * NTOT + n] = v;
    }
}

__global__ void copy_state_kernel(const float* __restrict__ src, float* __restrict__ dst)
{
    int i = blockIdx.x * 256 + threadIdx.x;
    dst[i] = src[i];
}

// ---------------------------------------------------------------------------
extern "C" void kernel_launch(void* const* d_in, const int* in_sizes, int n_in,
                              void* d_out, int out_size)
{
    const float* x        = (const float*)d_in[0];
    const float* gru_st   = (const float*)d_in[1];
    const float* done     = (const float*)d_in[2];
    const int*   action   = (const int*)  d_in[3];
    const float* w1       = (const float*)d_in[4];
    const float* b1       = (const float*)d_in[5];
    const float* w2       = (const float*)d_in[6];
    const float* b2       = (const float*)d_in[7];
    const float* w_ih     = (const float*)d_in[8];
    const float* w_hh     = (const float*)d_in[9];
    const float* b_ih     = (const float*)d_in[10];
    const float* b_hh     = (const float*)d_in[11];
    const float* w_actor  = (const float*)d_in[12];
    const float* b_actor  = (const float*)d_in[13];
    const float* w_critic = (const float*)d_in[14];
    const float* b_critic = (const float*)d_in[15];
    float* out = (float*)d_out;

    float *h1, *h2, *gx, *st;
    cudaGetSymbolAddress((void**)&h1, g_h1);
    cudaGetSymbolAddress((void**)&h2, g_h2);
    cudaGetSymbolAddress((void**)&gx, g_gx);
    cudaGetSymbolAddress((void**)&st, g_state);
    float* s0 = st;
    float* s1 = st + BATCH * HID;

    // encoder layer 1: (N,512)@(512,256)^T -> h1
    gemm_tf32_kernel<true><<<dim3(ENCD / 64, NTOT / 64), 128>>>(
        x, w1, b1, h1, NTOT, ENCD, OBSD);
    // encoder layer 2: (N,256)@(256,256)^T -> h2
    gemm_tf32_kernel<true><<<dim3(ENCD / 64, NTOT / 64), 128>>>(
        h1, w2, b2, h2, NTOT, ENCD, ENCD);
    // input-side gates: (N,256)@(256,1536)^T -> gx
    gemm_tf32_kernel<false><<<dim3(3 * HID / 64, NTOT / 64), 128>>>(
        h2, w_ih, b_ih, gx, NTOT, 3 * HID, ENCD);

    // GRU scan: 128 sequential fused steps
    for (int t = 0; t < T_STEPS; t++) {
        const float* sin = (t == 0) ? gru_st : ((t & 1) ? s1 : s0);
        float* sout = (t & 1) ? s0 : s1;
        gru_step_tf32<<<dim3(HID / 32, BATCH / 32), 128>>>(
            sin, sout, w_hh, b_hh, done, t);
    }
    copy_state_kernel<<<BATCH * HID / 256, 256>>>(s0, out + 3 * NTOT);

    heads_kernel<<<NTOT / 8, 256>>>(action, w_actor, b_actor, w_critic, b_critic, out);
}

// round 3
// speedup vs baseline: 3.2628x; 2.2573x over previous
#include <cuda_runtime.h>
#include <math.h>

#define T_STEPS 128
#define BATCH   256
#define OBSD    512
#define ENCD    256
#define HID     512
#define NACT    18
#define NTOT    (T_STEPS * BATCH)   // 32768

#define SCAN_GRID 128
#define WS_STRIDE 516
#define AS_STRIDE 36
#define GH_STRIDE 100
// smem floats: Ws 96*516 + As 2*32*36 + gh 32*100 + mask 32
#define SCAN_SMEM_FLOATS (96 * WS_STRIDE + 2 * 32 * AS_STRIDE + 32 * GH_STRIDE + 32)
#define SCAN_SMEM_BYTES  (SCAN_SMEM_FLOATS * 4)

// ---------------- scratch (static device globals; no runtime allocation) ----
__device__ float g_h1[(size_t)NTOT * ENCD];
__device__ float g_h2[(size_t)NTOT * ENCD];
__device__ float g_gx[(size_t)NTOT * 3 * HID];
__device__ float g_hidden[(size_t)NTOT * HID];
__device__ float g_state[2][BATCH * HID];
__device__ unsigned g_barrier;

// ---------------------------------------------------------------------------
__device__ __forceinline__ unsigned f2tf32(float f) {
    unsigned u;
    asm("cvt.rna.tf32.f32 %0, %1;" : "=r"(u) : "f"(f));
    return u;
}

__device__ __forceinline__ void mma_tf32(float d[4], const unsigned a[4], const unsigned b[2]) {
    asm volatile(
        "mma.sync.aligned.m16n8k8.row.col.f32.tf32.tf32.f32 "
        "{%0,%1,%2,%3}, {%4,%5,%6,%7}, {%8,%9}, {%0,%1,%2,%3};"
        : "+f"(d[0]), "+f"(d[1]), "+f"(d[2]), "+f"(d[3])
        : "r"(a[0]), "r"(a[1]), "r"(a[2]), "r"(a[3]), "r"(b[0]), "r"(b[1]));
}

__device__ __forceinline__ float sigmoidf_(float x) {
    return 1.f / (1.f + expf(-x));
}

__global__ void init_barrier_kernel() { g_barrier = 0u; }

// ---------------------------------------------------------------------------
// Generic C[M,Nc] = act(A[M,K] @ W[Nc,K]^T + bias) using tf32 mma.
// BM=64, BN=64, BK=16, 128 threads (4 warps, 2x2), warptile 32x32.
// ---------------------------------------------------------------------------
template <bool RELU>
__global__ __launch_bounds__(128)
void gemm_tf32_kernel(const float* __restrict__ A,
                      const float* __restrict__ W,
                      const float* __restrict__ bias,
                      float* __restrict__ C,
                      int M, int Nc, int K)
{
    __shared__ float As[64][18];
    __shared__ float Ws[64][18];

    const int tid  = threadIdx.x;
    const int warp = tid >> 5;
    const int lane = tid & 31;
    const int g    = lane >> 2;
    const int tg   = lane & 3;
    const int warp_m = (warp & 1) * 32;
    const int warp_n = (warp >> 1) * 32;
    const int row0 = blockIdx.y * 64;
    const int col0 = blockIdx.x * 64;

    float acc[2][4][4];
#pragma unroll
    for (int i = 0; i < 2; i++)
#pragma unroll
        for (int j = 0; j < 4; j++)
#pragma unroll
            for (int q = 0; q < 4; q++) acc[i][j][q] = 0.f;

    float4 ra[2], rw[2];
#pragma unroll
    for (int l = 0; l < 2; l++) {
        int i = tid + l * 128;
        ra[l] = *(const float4*)(A + (size_t)(row0 + (i >> 2)) * K + (i & 3) * 4);
        rw[l] = *(const float4*)(W + (size_t)(col0 + (i >> 2)) * K + (i & 3) * 4);
    }

    for (int k0 = 0; k0 < K; k0 += 16) {
#pragma unroll
        for (int l = 0; l < 2; l++) {
            int i = tid + l * 128;
            int r = i >> 2, c = (i & 3) * 4;
            As[r][c + 0] = __uint_as_float(f2tf32(ra[l].x));
            As[r][c + 1] = __uint_as_float(f2tf32(ra[l].y));
            As[r][c + 2] = __uint_as_float(f2tf32(ra[l].z));
            As[r][c + 3] = __uint_as_float(f2tf32(ra[l].w));
            Ws[r][c + 0] = __uint_as_float(f2tf32(rw[l].x));
            Ws[r][c + 1] = __uint_as_float(f2tf32(rw[l].y));
            Ws[r][c + 2] = __uint_as_float(f2tf32(rw[l].z));
            Ws[r][c + 3] = __uint_as_float(f2tf32(rw[l].w));
        }
        __syncthreads();

        if (k0 + 16 < K) {
#pragma unroll
            for (int l = 0; l < 2; l++) {
                int i = tid + l * 128;
                ra[l] = *(const float4*)(A + (size_t)(row0 + (i >> 2)) * K + k0 + 16 + (i & 3) * 4);
                rw[l] = *(const float4*)(W + (size_t)(col0 + (i >> 2)) * K + k0 + 16 + (i & 3) * 4);
            }
        }

#pragma unroll
        for (int ks = 0; ks < 16; ks += 8) {
            unsigned af[2][4], bf[4][2];
#pragma unroll
            for (int mf = 0; mf < 2; mf++) {
                int br = warp_m + mf * 16;
                af[mf][0] = __float_as_uint(As[br + g][ks + tg]);
                af[mf][1] = __float_as_uint(As[br + g + 8][ks + tg]);
                af[mf][2] = __float_as_uint(As[br + g][ks + tg + 4]);
                af[mf][3] = __float_as_uint(As[br + g + 8][ks + tg + 4]);
            }
#pragma unroll
            for (int nf = 0; nf < 4; nf++) {
                int bn = warp_n + nf * 8;
                bf[nf][0] = __float_as_uint(Ws[bn + g][ks + tg]);
                bf[nf][1] = __float_as_uint(Ws[bn + g][ks + tg + 4]);
            }
#pragma unroll
            for (int mf = 0; mf < 2; mf++)
#pragma unroll
                for (int nf = 0; nf < 4; nf++) mma_tf32(acc[mf][nf], af[mf], bf[nf]);
        }
        __syncthreads();
    }

#pragma unroll
    for (int mf = 0; mf < 2; mf++) {
#pragma unroll
        for (int nf = 0; nf < 4; nf++) {
            int r = row0 + warp_m + mf * 16 + g;
            int c = col0 + warp_n + nf * 8 + tg * 2;
            float b0v = bias[c], b1v = bias[c + 1];
            float v0 = acc[mf][nf][0] + b0v;
            float v1 = acc[mf][nf][1] + b1v;
            float v2 = acc[mf][nf][2] + b0v;
            float v3 = acc[mf][nf][3] + b1v;
            if (RELU) {
                v0 = fmaxf(v0, 0.f); v1 = fmaxf(v1, 0.f);
                v2 = fmaxf(v2, 0.f); v3 = fmaxf(v3, 0.f);
            }
            *(float2*)&C[(size_t)r * Nc + c]       = make_float2(v0, v1);
            *(float2*)&C[(size_t)(r + 8) * Nc + c] = make_float2(v2, v3);
        }
    }
}

// ---------------------------------------------------------------------------
// Persistent GRU scan. 128 blocks (16 hcol x 8 batch), 256 threads (8 warps).
// w_hh slice (96 x 512) resident in smem as tf32 for all 128 timesteps.
// Software grid barrier between steps.
// ---------------------------------------------------------------------------
__global__ __launch_bounds__(256)
void gru_scan_kernel(const float* __restrict__ gru_st,
                     const float* __restrict__ w_hh,
                     const float* __restrict__ b_hh,
                     const float* __restrict__ done)
{
    extern __shared__ float sm[];
    float* Ws     = sm;                                  // [96][WS_STRIDE]
    float* Asm    = Ws + 96 * WS_STRIDE;                 // [2][32][AS_STRIDE]
    float* ghs    = Asm + 2 * 32 * AS_STRIDE;            // [32][GH_STRIDE]
    float* s_mask = ghs + 32 * GH_STRIDE;                // [32]

    const int tid  = threadIdx.x;
    const int warp = tid >> 5;
    const int lane = tid & 31;
    const int g    = lane >> 2;
    const int tg   = lane & 3;
    const int bid  = blockIdx.x;
    const int col0 = (bid & 15) * 32;     // h-col block
    const int row0 = (bid >> 4) * 32;     // batch block
    const int warp_m = (warp & 1) * 16;
    const int warp_n = (warp >> 1) * 24;

    // ---- preload w_hh slice (96 rows x 512 K) as tf32 ----
    for (int i = tid; i < 96 * 128; i += 256) {
        int r  = i >> 7;
        int c4 = (i & 127) * 4;
        int gg = r >> 5, lr = r & 31;
        float4 v = *(const float4*)(w_hh + (size_t)(gg * HID + col0 + lr) * HID + c4);
        float* d = Ws + r * WS_STRIDE + c4;
        d[0] = __uint_as_float(f2tf32(v.x));
        d[1] = __uint_as_float(f2tf32(v.y));
        d[2] = __uint_as_float(f2tf32(v.z));
        d[3] = __uint_as_float(f2tf32(v.w));
    }
    __syncthreads();

    const int r_a  = tid >> 3;           // 0..31 (batch row within tile)
    const int c4a  = (tid & 7) * 4;      // k offset within 32-chunk

    float* sb0 = g_state[0];
    float* sb1 = g_state[1];

    for (int t = 0; t < T_STEPS; t++) {
        const float* sin = (t == 0) ? gru_st : ((t & 1) ? sb1 : sb0);
        float*       sout = (t & 1) ? sb0 : sb1;

        if (tid < 32) s_mask[tid] = 1.0f - __ldg(done + t * BATCH + row0 + tid);
        __syncthreads();

        float acc[3][4];
#pragma unroll
        for (int nf = 0; nf < 3; nf++)
#pragma unroll
            for (int q = 0; q < 4; q++) acc[nf][q] = 0.f;

        const float m_a = s_mask[r_a];
        const float* arow = sin + (size_t)(row0 + r_a) * HID;
        float4 ra = __ldcg((const float4*)(arow + c4a));

#pragma unroll 4
        for (int kk = 0; kk < 16; kk++) {
            float* Ab = Asm + (kk & 1) * (32 * AS_STRIDE);
            float* d  = Ab + r_a * AS_STRIDE + c4a;
            d[0] = __uint_as_float(f2tf32(ra.x * m_a));
            d[1] = __uint_as_float(f2tf32(ra.y * m_a));
            d[2] = __uint_as_float(f2tf32(ra.z * m_a));
            d[3] = __uint_as_float(f2tf32(ra.w * m_a));
            if (kk < 15)
                ra = __ldcg((const float4*)(arow + (kk + 1) * 32 + c4a));
            __syncthreads();

            const float* Am0 = Ab + (warp_m + g) * AS_STRIDE;
            const float* Am1 = Ab + (warp_m + g + 8) * AS_STRIDE;
#pragma unroll
            for (int ks = 0; ks < 32; ks += 8) {
                unsigned af[4];
                af[0] = __float_as_uint(Am0[ks + tg]);
                af[1] = __float_as_uint(Am1[ks + tg]);
                af[2] = __float_as_uint(Am0[ks + tg + 4]);
                af[3] = __float_as_uint(Am1[ks + tg + 4]);
#pragma unroll
                for (int nf = 0; nf < 3; nf++) {
                    const float* Wr = Ws + (size_t)(warp_n + nf * 8 + g) * WS_STRIDE + kk * 32 + ks + tg;
                    unsigned bf[2];
                    bf[0] = __float_as_uint(Wr[0]);
                    bf[1] = __float_as_uint(Wr[4]);
                    mma_tf32(acc[nf], af, bf);
                }
            }
        }

        // stage gh into smem (combined cols: 0..31 r, 32..63 z, 64..95 n)
#pragma unroll
        for (int nf = 0; nf < 3; nf++) {
            int c = warp_n + nf * 8 + tg * 2;
            int r = warp_m + g;
            ghs[r * GH_STRIDE + c]           = acc[nf][0];
            ghs[r * GH_STRIDE + c + 1]       = acc[nf][1];
            ghs[(r + 8) * GH_STRIDE + c]     = acc[nf][2];
            ghs[(r + 8) * GH_STRIDE + c + 1] = acc[nf][3];
        }
        __syncthreads();

        // fused gate math: thread -> batch row b, 4 h-cols
        {
            const int b  = tid >> 3;
            const int c  = (tid & 7) * 4;
            const int bg = row0 + b;
            const float m = s_mask[b];
            const float* gxr = g_gx + ((size_t)t * BATCH + bg) * (3 * HID);
            float4 xr  = *(const float4*)(gxr + col0 + c);
            float4 xz  = *(const float4*)(gxr + HID + col0 + c);
            float4 xn  = *(const float4*)(gxr + 2 * HID + col0 + c);
            float4 br_ = *(const float4*)(b_hh + col0 + c);
            float4 bz_ = *(const float4*)(b_hh + HID + col0 + c);
            float4 bn_ = *(const float4*)(b_hh + 2 * HID + col0 + c);
            float4 hp4 = __ldcg((const float4*)(sin + (size_t)bg * HID + col0 + c));

            float xrf[4] = {xr.x, xr.y, xr.z, xr.w};
            float xzf[4] = {xz.x, xz.y, xz.z, xz.w};
            float xnf[4] = {xn.x, xn.y, xn.z, xn.w};
            float brf[4] = {br_.x, br_.y, br_.z, br_.w};
            float bzf[4] = {bz_.x, bz_.y, bz_.z, bz_.w};
            float bnf[4] = {bn_.x, bn_.y, bn_.z, bn_.w};
            float hpf[4] = {hp4.x, hp4.y, hp4.z, hp4.w};
            float hnew[4];
#pragma unroll
            for (int j = 0; j < 4; j++) {
                float ghr = ghs[b * GH_STRIDE + c + j] + brf[j];
                float ghz = ghs[b * GH_STRIDE + 32 + c + j] + bzf[j];
                float ghn = ghs[b * GH_STRIDE + 64 + c + j] + bnf[j];
                float r = sigmoidf_(xrf[j] + ghr);
                float z = sigmoidf_(xzf[j] + ghz);
                float n = tanhf(xnf[j] + r * ghn);
                hnew[j] = (1.f - z) * n + z * (hpf[j] * m);
            }
            float4 o = make_float4(hnew[0], hnew[1], hnew[2], hnew[3]);
            *(float4*)(sout + (size_t)bg * HID + col0 + c) = o;
            *(float4*)(g_hidden + ((size_t)t * BATCH + bg) * HID + col0 + c) = o;
        }

        // ---- grid barrier ----
        __threadfence();
        __syncthreads();
        if (tid == 0) {
            atomicAdd(&g_barrier, 1u);
            unsigned target = (unsigned)SCAN_GRID * (unsigned)(t + 1);
            while (*(volatile unsigned*)&g_barrier < target) { }
            __threadfence();
        }
        __syncthreads();
    }
}

// ---------------------------------------------------------------------------
// Heads: one warp per row n.
// ---------------------------------------------------------------------------
__global__ __launch_bounds__(256)
void heads_kernel(const int* __restrict__ action,
                  const float* __restrict__ w_actor,
                  const float* __restrict__ b_actor,
                  const float* __restrict__ w_critic,
                  const float* __restrict__ b_critic,
                  float* __restrict__ out)
{
    __shared__ float s_wa[NACT * HID];
    __shared__ float s_wc[HID];
    __shared__ float s_ba[NACT];

    const int tid = threadIdx.x;
    for (int i = tid; i < NACT * HID; i += 256) s_wa[i] = w_actor[i];
    for (int i = tid; i < HID; i += 256) s_wc[i] = w_critic[i];
    if (tid < NACT) s_ba[tid] = b_actor[tid];
    __syncthreads();

    const int warp = tid >> 5;
    const int lane = tid & 31;
    const int n = blockIdx.x * 8 + warp;

    const float* hrow = g_hidden + (size_t)n * HID;
    float h[16];
#pragma unroll
    for (int i = 0; i < 16; i++) h[i] = hrow[lane + 32 * i];

    float l[NACT];
#pragma unroll
    for (int a = 0; a < NACT; a++) {
        float p = 0.f;
        const float* wa = s_wa + a * HID;
#pragma unroll
        for (int i = 0; i < 16; i++) p += h[i] * wa[lane + 32 * i];
#pragma unroll
        for (int o = 16; o > 0; o >>= 1) p += __shfl_xor_sync(0xffffffffu, p, o);
        l[a] = p + s_ba[a];
    }

    float v = 0.f;
#pragma unroll
    for (int i = 0; i < 16; i++) v += h[i] * s_wc[lane + 32 * i];
#pragma unroll
    for (int o = 16; o > 0; o >>= 1) v += __shfl_xor_sync(0xffffffffu, v, o);
    v += b_critic[0];

    float mx = l[0];
#pragma unroll
    for (int a = 1; a < NACT; a++) mx = fmaxf(mx, l[a]);
    float s = 0.f;
#pragma unroll
    for (int a = 0; a < NACT; a++) s += expf(l[a] - mx);
    float lse = mx + logf(s);

    float ent = 0.f;
#pragma unroll
    for (int a = 0; a < NACT; a++) ent += expf(l[a] - lse) * (lse - l[a]);

    int act = action[n];
    float lp = 0.f;
#pragma unroll
    for (int a = 0; a < NACT; a++) lp += (a == act) ? (l[a] - lse) : 0.f;

    if (lane == 0) {
        out[n] = lp;
        out[NTOT + n] = ent;
        out[2 * NTOT + n] = v;
    }
}

__global__ void copy_state_kernel(const float* __restrict__ src, float* __restrict__ dst)
{
    int i = blockIdx.x * 256 + threadIdx.x;
    dst[i] = src[i];
}

// ---------------------------------------------------------------------------
extern "C" void kernel_launch(void* const* d_in, const int* in_sizes, int n_in,
                              void* d_out, int out_size)
{
    const float* x        = (const float*)d_in[0];
    const float* gru_st   = (const float*)d_in[1];
    const float* done     = (const float*)d_in[2];
    const int*   action   = (const int*)  d_in[3];
    const float* w1       = (const float*)d_in[4];
    const float* b1       = (const float*)d_in[5];
    const float* w2       = (const float*)d_in[6];
    const float* b2       = (const float*)d_in[7];
    const float* w_ih     = (const float*)d_in[8];
    const float* w_hh     = (const float*)d_in[9];
    const float* b_ih     = (const float*)d_in[10];
    const float* b_hh     = (const float*)d_in[11];
    const float* w_actor  = (const float*)d_in[12];
    const float* b_actor  = (const float*)d_in[13];
    const float* w_critic = (const float*)d_in[14];
    const float* b_critic = (const float*)d_in[15];
    float* out = (float*)d_out;

    float *h1, *h2, *gx, *st;
    cudaGetSymbolAddress((void**)&h1, g_h1);
    cudaGetSymbolAddress((void**)&h2, g_h2);
    cudaGetSymbolAddress((void**)&gx, g_gx);
    cudaGetSymbolAddress((void**)&st, g_state);
    float* s0 = st;

    static int smem_set = 0;
    if (!smem_set) {
        cudaFuncSetAttribute(gru_scan_kernel,
                             cudaFuncAttributeMaxDynamicSharedMemorySize,
                             SCAN_SMEM_BYTES);
        smem_set = 1;
    }

    // encoder layer 1: (N,512)@(512,256)^T -> h1
    gemm_tf32_kernel<true><<<dim3(ENCD / 64, NTOT / 64), 128>>>(
        x, w1, b1, h1, NTOT, ENCD, OBSD);
    // encoder layer 2: (N,256)@(256,256)^T -> h2
    gemm_tf32_kernel<true><<<dim3(ENCD / 64, NTOT / 64), 128>>>(
        h1, w2, b2, h2, NTOT, ENCD, ENCD);
    // input-side gates: (N,256)@(256,1536)^T -> gx
    gemm_tf32_kernel<false><<<dim3(3 * HID / 64, NTOT / 64), 128>>>(
        h2, w_ih, b_ih, gx, NTOT, 3 * HID, ENCD);

    // persistent GRU scan
    init_barrier_kernel<<<1, 1>>>();
    gru_scan_kernel<<<SCAN_GRID, 256, SCAN_SMEM_BYTES>>>(gru_st, w_hh, b_hh, done);

    // final state (t=127 wrote g_state[0])
    copy_state_kernel<<<BATCH * HID / 256, 256>>>(s0, out + 3 * NTOT);

    heads_kernel<<<NTOT / 8, 256>>>(action, w_actor, b_actor, w_critic, b_critic, out);
}